// round 8
// baseline (speedup 1.0000x reference)
#include <cuda_runtime.h>
#include <cuda_bf16.h>
#include <cstdint>
#include <cstddef>

#define B_TOT 32768
#define D_IN  128
#define A_DIM 16
#define H1D   600
#define H2D   500
#define KP    640
#define G_N   8

// ---- h1 geometry (CK=64, proven R4/R6) ----
#define H1_ROWB   144u
#define H1_AHALF  18432u   // 128*144
#define H1_BHALF  9216u    // 64*144
#define H1_STAGE  (2u*H1_AHALF + 2u*H1_BHALF)   // 55296
#define H1_SMEM   (2*H1_STAGE + 1024)

// ---- h2q geometry (CK=32, M=128 x N=128 with shared A) ----
#define H2_ROWB   80u
#define H2_AHALF  10240u   // 128*80
#define H2_BQUAR  5120u    // 64*80
#define H2_STAGE  (2u*H2_AHALF + 4u*H2_BQUAR)   // 40960
#define H2_SMEM   (2*H2_STAGE + 1536)

// ---- persistent device scratch (pre-split bf16 hi/lo operands) ----
__device__ __nv_bfloat16 g_h1hi[(size_t)B_TOT * KP];
__device__ __nv_bfloat16 g_h1lo[(size_t)B_TOT * KP];
__device__ __nv_bfloat16 g_Sh[(size_t)B_TOT * D_IN];
__device__ __nv_bfloat16 g_Sl[(size_t)B_TOT * D_IN];
__device__ __nv_bfloat16 g_W1h[(size_t)G_N * 640 * D_IN];
__device__ __nv_bfloat16 g_W1l[(size_t)G_N * 640 * D_IN];
__device__ __nv_bfloat16 g_W2h[(size_t)512 * 576];
__device__ __nv_bfloat16 g_W2l[(size_t)512 * 576];
__device__ __nv_bfloat16 g_Bth[(size_t)G_N * 512 * 64];
__device__ __nv_bfloat16 g_Btl[(size_t)G_N * 512 * 64];

// ---------------- helpers ----------------
__device__ __forceinline__ uint32_t smem_u32(const void* p) {
    uint32_t a;
    asm("{ .reg .u64 t; cvta.to.shared.u64 t, %1; cvt.u32.u64 %0, t; }" : "=r"(a) : "l"(p));
    return a;
}
__device__ __forceinline__ void ldm_x4(uint32_t* r, uint32_t addr) {
    asm volatile("ldmatrix.sync.aligned.m8n8.x4.shared.b16 {%0,%1,%2,%3}, [%4];"
                 : "=r"(r[0]), "=r"(r[1]), "=r"(r[2]), "=r"(r[3]) : "r"(addr));
}
__device__ __forceinline__ void mma16816(float* c, const uint32_t* a, const uint32_t* b) {
    asm volatile("mma.sync.aligned.m16n8k16.row.col.f32.bf16.bf16.f32 "
                 "{%0,%1,%2,%3}, {%4,%5,%6,%7}, {%8,%9}, {%0,%1,%2,%3};"
                 : "+f"(c[0]), "+f"(c[1]), "+f"(c[2]), "+f"(c[3])
                 : "r"(a[0]), "r"(a[1]), "r"(a[2]), "r"(a[3]), "r"(b[0]), "r"(b[1]));
}
__device__ __forceinline__ void cp16(uint32_t dst, const void* src) {
    asm volatile("cp.async.cg.shared.global [%0], [%1], 16;" :: "r"(dst), "l"(src) : "memory");
}
__device__ __forceinline__ void cp_commit() { asm volatile("cp.async.commit_group;" ::: "memory"); }
__device__ __forceinline__ void cp_wait0() { asm volatile("cp.async.wait_group 0;" ::: "memory"); }

__device__ __forceinline__ uint32_t pack2(float f0, float f1) {
    uint32_t r;
    asm("cvt.rn.bf16x2.f32 %0, %1, %2;" : "=r"(r) : "f"(f1), "f"(f0));
    return r;
}
__device__ __forceinline__ void split2(float f0, float f1, uint32_t& h, uint32_t& l) {
    h = pack2(f0, f1);
    float h0 = __uint_as_float(h << 16);
    float h1 = __uint_as_float(h & 0xffff0000u);
    l = pack2(f0 - h0, f1 - h1);
}
__device__ __forceinline__ void split8(float4 v0, float4 v1, uint4& H, uint4& L) {
    split2(v0.x, v0.y, H.x, L.x);
    split2(v0.z, v0.w, H.y, L.y);
    split2(v1.x, v1.y, H.z, L.z);
    split2(v1.z, v1.w, H.w, L.w);
}

// ---------------- fused prep kernel ----------------
#define PREP_BLOCKS 2896
__global__ __launch_bounds__(256) void prep_kernel(const float* __restrict__ state,
                                                   const float* __restrict__ action,
                                                   const int* __restrict__ idx,
                                                   const float* __restrict__ W1,
                                                   const float* __restrict__ W2s,
                                                   const float* __restrict__ W2a,
                                                   const float* __restrict__ b3,
                                                   float* __restrict__ out) {
    const int blk = blockIdx.x;
    const int t = threadIdx.x;
    if (blk < 128) {
        int i = blk * 256 + t;
        out[i] = b3[idx[i]];
    } else if (blk < 256) {
        int b = (blk - 128) * 256 + t;
        const float4* a4 = (const float4*)(action + (size_t)b * A_DIM);
        uint4 H0, L0, H1, L1;
        split8(a4[0], a4[1], H0, L0);
        split8(a4[2], a4[3], H1, L1);
        uint16_t* ph = (uint16_t*)g_h1hi + (size_t)b * KP + 600;
        uint16_t* pl = (uint16_t*)g_h1lo + (size_t)b * KP + 600;
        ((uint4*)ph)[0] = H0; ((uint4*)ph)[1] = H1;
        ((uint4*)pl)[0] = L0; ((uint4*)pl)[1] = L1;
        uint4 z = make_uint4(0, 0, 0, 0);
        ((uint4*)(ph + 16))[0] = z; ((uint4*)(ph + 16))[1] = z; ((uint4*)(ph + 16))[2] = z;
        ((uint4*)(pl + 16))[0] = z; ((uint4*)(pl + 16))[1] = z; ((uint4*)(pl + 16))[2] = z;
    } else if (blk < 2304) {
        size_t e = ((size_t)(blk - 256) * 256 + t) * 8;
        const float4* s4 = (const float4*)(state + e);
        uint4 H, L;
        split8(s4[0], s4[1], H, L);
        *(uint4*)((uint16_t*)g_Sh + e) = H;
        *(uint4*)((uint16_t*)g_Sl + e) = L;
    } else if (blk < 2624) {
        size_t e = ((size_t)(blk - 2304) * 256 + t) * 8;
        int g = (int)(e / (640 * D_IN));
        int r = (int)((e / D_IN) % 640);
        int c = (int)(e % D_IN);
        uint4 H = make_uint4(0, 0, 0, 0), L = H;
        if (r < H1D) {
            const float4* s4 = (const float4*)(W1 + ((size_t)g * H1D + r) * D_IN + c);
            split8(s4[0], s4[1], H, L);
        }
        *(uint4*)((uint16_t*)g_W1h + e) = H;
        *(uint4*)((uint16_t*)g_W1l + e) = L;
    } else if (blk < 2768) {
        size_t e = ((size_t)(blk - 2624) * 256 + t) * 8;
        int n = (int)(e / 576);
        int c = (int)(e % 576);
        uint4 H = make_uint4(0, 0, 0, 0), L = H;
        if (n < H2D) {
            const float4* s4 = (const float4*)(W2s + (size_t)n * H1D + c);
            split8(s4[0], s4[1], H, L);
        }
        *(uint4*)((uint16_t*)g_W2h + e) = H;
        *(uint4*)((uint16_t*)g_W2l + e) = L;
    } else {
        size_t e = ((size_t)(blk - 2768) * 256 + t) * 8;
        int g = (int)(e / (512 * 64));
        int n = (int)((e / 64) % 512);
        int cc = (int)(e % 64);
        float v[8];
        #pragma unroll
        for (int j = 0; j < 8; j++) {
            int c = cc + j;
            float x = 0.f;
            if (n < H2D) {
                if (c < 24) x = W2s[(size_t)n * H1D + 576 + c];
                else if (c < 40) x = W2a[((size_t)g * H2D + n) * A_DIM + (c - 24)];
            }
            v[j] = x;
        }
        uint4 H, L;
        split8(make_float4(v[0], v[1], v[2], v[3]), make_float4(v[4], v[5], v[6], v[7]), H, L);
        *(uint4*)((uint16_t*)g_Bth + e) = H;
        *(uint4*)((uint16_t*)g_Btl + e) = L;
    }
}

// ================= GEMM1 (R6-proven): M=128,N=64,K=128, CK=64, 2 stages =================
#define MMA_STAGE1(sbase, s)                                                       \
    {                                                                              \
        const uint32_t SA = (sbase) + (uint32_t)(s) * H1_STAGE;                    \
        const uint32_t SAh = SA, SAl = SA + H1_AHALF;                              \
        const uint32_t SBh = SA + 2u * H1_AHALF, SBl = SBh + H1_BHALF;             \
        _Pragma("unroll")                                                          \
        for (int kk = 0; kk < 4; kk++) {                                           \
            uint32_t ah[2][4], al[2][4], bh[4][2], bl[4][2];                       \
            _Pragma("unroll")                                                      \
            for (int mf = 0; mf < 2; mf++) {                                       \
                ldm_x4(ah[mf], SAh + aoff + mf * 2304u + kk * 32u);                \
                ldm_x4(al[mf], SAl + aoff + mf * 2304u + kk * 32u);                \
            }                                                                      \
            _Pragma("unroll")                                                      \
            for (int nq = 0; nq < 2; nq++) {                                       \
                uint32_t t[4];                                                     \
                ldm_x4(t, SBh + boff + nq * 2304u + kk * 32u);                     \
                bh[nq * 2][0] = t[0]; bh[nq * 2][1] = t[2];                        \
                bh[nq * 2 + 1][0] = t[1]; bh[nq * 2 + 1][1] = t[3];                \
                ldm_x4(t, SBl + boff + nq * 2304u + kk * 32u);                     \
                bl[nq * 2][0] = t[0]; bl[nq * 2][1] = t[2];                        \
                bl[nq * 2 + 1][0] = t[1]; bl[nq * 2 + 1][1] = t[3];                \
            }                                                                      \
            _Pragma("unroll")                                                      \
            for (int mf = 0; mf < 2; mf++)                                         \
                _Pragma("unroll")                                                  \
                for (int nf = 0; nf < 4; nf++) {                                   \
                    mma16816(C[mf][nf], ah[mf], bh[nf]);                           \
                    mma16816(C[mf][nf], ah[mf], bl[nf]);                           \
                    mma16816(C[mf][nf], al[mf], bh[nf]);                           \
                }                                                                  \
        }                                                                          \
    }

__global__ __launch_bounds__(256, 2) void h1_mma_kernel(const int* __restrict__ idx,
                                                        const float* __restrict__ b1) {
    extern __shared__ char dsm[];
    const uint32_t sbase = smem_u32(dsm);
    float* sb1 = (float*)(dsm + 2 * H1_STAGE);
    int* sidx = (int*)(sb1 + 64);
    const int tid = threadIdx.x, lane = tid & 31, wid = tid >> 5;
    const int n0 = blockIdx.x * 64, b0 = blockIdx.y * 128;
    if (tid < 128) sidx[tid] = idx[b0 + tid];
    __syncthreads();
    const int g_lo = sidx[0], g_hi = sidx[127];
    const int m_base = (wid >> 1) * 32, n_base = (wid & 1) * 32;
    const uint32_t aoff = (uint32_t)(m_base + (lane & 15)) * H1_ROWB + (uint32_t)((lane >> 4) * 16);
    const uint32_t boff = (uint32_t)(n_base + (lane & 15)) * H1_ROWB + (uint32_t)((lane >> 4) * 16);

    for (int g = g_lo; g <= g_hi; ++g) {
        if (tid < 64) { int n = n0 + tid; sb1[tid] = (n < H1D) ? b1[(size_t)g * H1D + n] : 0.f; }
        auto issue = [&](int kc, int s) {
            #pragma unroll
            for (int i = 0; i < 8; i++) {
                int bid = tid + i * 256;
                int arr = bid >> 10, rem = bid & 1023;
                int row = rem >> 3, q = rem & 7;
                const __nv_bfloat16* src = (arr ? g_Sl : g_Sh) + (size_t)(b0 + row) * D_IN + kc * 64 + q * 8;
                cp16(sbase + (uint32_t)s * H1_STAGE + (uint32_t)arr * H1_AHALF + row * H1_ROWB + q * 16u, src);
            }
            #pragma unroll
            for (int i = 0; i < 4; i++) {
                int bid = tid + i * 256;
                int arr = bid >> 9, rem = bid & 511;
                int row = rem >> 3, q = rem & 7;
                const __nv_bfloat16* src = (arr ? g_W1l : g_W1h) + ((size_t)g * 640 + n0 + row) * D_IN + kc * 64 + q * 8;
                cp16(sbase + (uint32_t)s * H1_STAGE + 2u * H1_AHALF + (uint32_t)arr * H1_BHALF + row * H1_ROWB + q * 16u, src);
            }
            cp_commit();
        };
        float C[2][4][4];
        #pragma unroll
        for (int mf = 0; mf < 2; mf++)
            #pragma unroll
            for (int nf = 0; nf < 4; nf++)
                #pragma unroll
                for (int e = 0; e < 4; e++) C[mf][nf][e] = 0.f;

        issue(0, 0);
        cp_wait0();
        __syncthreads();
        issue(1, 1);
        MMA_STAGE1(sbase, 0);
        cp_wait0();
        __syncthreads();
        MMA_STAGE1(sbase, 1);

        #pragma unroll
        for (int mf = 0; mf < 2; mf++)
            #pragma unroll
            for (int half = 0; half < 2; half++) {
                int r = m_base + mf * 16 + (lane >> 2) + half * 8;
                if (sidx[r] == g) {
                    size_t base = (size_t)(b0 + r) * KP;
                    #pragma unroll
                    for (int nf = 0; nf < 4; nf++) {
                        int lc = n_base + nf * 8 + 2 * (lane & 3);
                        int n = n0 + lc;
                        if (n < H1D) {
                            float v0 = fmaxf(C[mf][nf][half * 2 + 0] + sb1[lc], 0.f);
                            float v1 = fmaxf(C[mf][nf][half * 2 + 1] + sb1[lc + 1], 0.f);
                            uint32_t h, l;
                            split2(v0, v1, h, l);
                            *(uint32_t*)(g_h1hi + base + n) = h;
                            *(uint32_t*)(g_h1lo + base + n) = l;
                        }
                    }
                }
            }
        __syncthreads();
    }
}

// ================= GEMM2: M=128 x N=128 (two 64-col tiles share A), CK=32 =================
__global__ __launch_bounds__(256, 2) void h2q_mma_kernel(const int* __restrict__ idx,
                                                         const float* __restrict__ b2s,
                                                         const float* __restrict__ W3,
                                                         float* __restrict__ out) {
    extern __shared__ char dsm[];
    const uint32_t sbase = smem_u32(dsm);
    float* sb2 = (float*)(dsm + 2 * H2_STAGE);
    float* sw3 = sb2 + 128;
    int* sidx = (int*)(sw3 + 128);
    const int tid = threadIdx.x, lane = tid & 31, wid = tid >> 5;
    const int n0p = blockIdx.x * 128, b0 = blockIdx.y * 128;
    if (tid < 128) {
        sidx[tid] = idx[b0 + tid];
        int n = n0p + tid;
        sb2[tid] = (n < H2D) ? b2s[n] : 0.f;
    }
    __syncthreads();
    const int g_lo = sidx[0], g_hi = sidx[127];
    const int m_base = (wid >> 1) * 32, n_base = (wid & 1) * 32;
    const uint32_t aoff = (uint32_t)(m_base + (lane & 15)) * H2_ROWB + (uint32_t)((lane >> 4) * 16);
    const uint32_t boff = (uint32_t)(n_base + (lane & 15)) * H2_ROWB + (uint32_t)((lane >> 4) * 16);

    // ---- hoisted cp.async slot geometry ----
    // A: 4 slots over 1024 16B-blocks (2 arrays x 128 rows x 4 q)
    uint32_t dstA[4], ofsA[4];  // ofsA: byte offset within g_h1{hi,lo}
    #pragma unroll
    for (int i = 0; i < 4; i++) {
        int bid = tid + i * 256;
        int arr = bid >> 9, rem = bid & 511, row = rem >> 2, q = rem & 3;
        dstA[i] = (uint32_t)arr * H2_AHALF + (uint32_t)row * H2_ROWB + (uint32_t)q * 16u;
        ofsA[i] = (uint32_t)(((b0 + row) * KP + q * 8) * 2) | ((uint32_t)arr << 31);
    }
    // B: 4 slots over 1024 blocks (2 tiles x 2 arrays x 64 rows x 4 q)
    uint32_t dstB[4], ofsW2[4], ofsBt[4], barrB[4];
    #pragma unroll
    for (int i = 0; i < 4; i++) {
        int bid = tid + i * 256;
        int t = bid >> 9, rem = bid & 511, arr = rem >> 8, rem2 = rem & 255;
        int row = rem2 >> 2, q = rem2 & 3;
        barrB[i] = (uint32_t)arr;
        dstB[i] = 2u * H2_AHALF + (uint32_t)(t * 2 + arr) * H2_BQUAR + (uint32_t)row * H2_ROWB + (uint32_t)q * 16u;
        int nrow = n0p + t * 64 + row;
        ofsW2[i] = (uint32_t)((nrow * 576 + q * 8) * 2);
        ofsBt[i] = (uint32_t)((nrow * 64 + q * 8) * 2);
    }
    const char* baseAh = (const char*)g_h1hi;
    const char* baseAl = (const char*)g_h1lo;
    const char* baseW2h = (const char*)g_W2h;
    const char* baseW2l = (const char*)g_W2l;

    for (int g = g_lo; g <= g_hi; ++g) {
        if (tid < 128) { int n = n0p + tid; sw3[tid] = (n < H2D) ? W3[(size_t)g * H2D + n] : 0.f; }
        const char* baseBth = (const char*)(g_Bth + (size_t)g * 512 * 64);
        const char* baseBtl = (const char*)(g_Btl + (size_t)g * 512 * 64);

        auto issue = [&](int kc, int s) {
            const uint32_t sb = sbase + (uint32_t)s * H2_STAGE;
            const uint32_t ko = (uint32_t)kc * 64u;  // bytes per chunk step
            #pragma unroll
            for (int i = 0; i < 4; i++) {
                const char* src = ((ofsA[i] >> 31) ? baseAl : baseAh) + (ofsA[i] & 0x7fffffffu) + ko;
                cp16(sb + dstA[i], src);
            }
            if (kc < 18) {
                #pragma unroll
                for (int i = 0; i < 4; i++) {
                    const char* src = (barrB[i] ? baseW2l : baseW2h) + ofsW2[i] + ko;
                    cp16(sb + dstB[i], src);
                }
            } else {
                const uint32_t kt = (uint32_t)(kc - 18) * 64u;
                #pragma unroll
                for (int i = 0; i < 4; i++) {
                    const char* src = (barrB[i] ? baseBtl : baseBth) + ofsBt[i] + kt;
                    cp16(sb + dstB[i], src);
                }
            }
            cp_commit();
        };

        float C[2][2][4][4];  // [tile][mf][nf][e]
        #pragma unroll
        for (int t = 0; t < 2; t++)
            #pragma unroll
            for (int mf = 0; mf < 2; mf++)
                #pragma unroll
                for (int nf = 0; nf < 4; nf++)
                    #pragma unroll
                    for (int e = 0; e < 4; e++) C[t][mf][nf][e] = 0.f;

        issue(0, 0);
        for (int kc = 0; kc < 20; ++kc) {
            cp_wait0();
            __syncthreads();
            if (kc < 19) issue(kc + 1, (kc + 1) & 1);
            {
                const uint32_t SA = sbase + (uint32_t)(kc & 1) * H2_STAGE;
                const uint32_t SAh = SA, SAl = SA + H2_AHALF;
                #pragma unroll
                for (int kk = 0; kk < 2; kk++) {
                    uint32_t ah[2][4], al[2][4];
                    #pragma unroll
                    for (int mf = 0; mf < 2; mf++) {
                        ldm_x4(ah[mf], SAh + aoff + mf * 1280u + kk * 32u);
                        ldm_x4(al[mf], SAl + aoff + mf * 1280u + kk * 32u);
                    }
                    #pragma unroll
                    for (int t = 0; t < 2; t++) {
                        const uint32_t SBh = SA + 2u * H2_AHALF + (uint32_t)(t * 2) * H2_BQUAR;
                        const uint32_t SBl = SBh + H2_BQUAR;
                        uint32_t bh[4][2], bl[4][2];
                        #pragma unroll
                        for (int nq = 0; nq < 2; nq++) {
                            uint32_t tt[4];
                            ldm_x4(tt, SBh + boff + nq * 1280u + kk * 32u);
                            bh[nq * 2][0] = tt[0]; bh[nq * 2][1] = tt[2];
                            bh[nq * 2 + 1][0] = tt[1]; bh[nq * 2 + 1][1] = tt[3];
                            ldm_x4(tt, SBl + boff + nq * 1280u + kk * 32u);
                            bl[nq * 2][0] = tt[0]; bl[nq * 2][1] = tt[2];
                            bl[nq * 2 + 1][0] = tt[1]; bl[nq * 2 + 1][1] = tt[3];
                        }
                        #pragma unroll
                        for (int mf = 0; mf < 2; mf++)
                            #pragma unroll
                            for (int nf = 0; nf < 4; nf++) {
                                mma16816(C[t][mf][nf], ah[mf], bh[nf]);
                                mma16816(C[t][mf][nf], ah[mf], bl[nf]);
                                mma16816(C[t][mf][nf], al[mf], bh[nf]);
                            }
                    }
                }
            }
        }

        // epilogue: relu(+b2s) . W3 over both tiles, quad-reduce, atomicAdd
        #pragma unroll
        for (int mf = 0; mf < 2; mf++)
            #pragma unroll
            for (int half = 0; half < 2; half++) {
                int r = m_base + mf * 16 + (lane >> 2) + half * 8;
                float qp = 0.f;
                #pragma unroll
                for (int t = 0; t < 2; t++)
                    #pragma unroll
                    for (int nf = 0; nf < 4; nf++) {
                        int lc = t * 64 + n_base + nf * 8 + 2 * (lane & 3);
                        qp += fmaxf(C[t][mf][nf][half * 2 + 0] + sb2[lc], 0.f) * sw3[lc];
                        qp += fmaxf(C[t][mf][nf][half * 2 + 1] + sb2[lc + 1], 0.f) * sw3[lc + 1];
                    }
                qp += __shfl_xor_sync(0xffffffffu, qp, 1);
                qp += __shfl_xor_sync(0xffffffffu, qp, 2);
                if ((lane & 3) == 0 && sidx[r] == g) atomicAdd(out + b0 + r, qp);
            }
        __syncthreads();
    }
}

extern "C" void kernel_launch(void* const* d_in, const int* in_sizes, int n_in,
                              void* d_out, int out_size) {
    const float* state  = (const float*)d_in[0];
    const float* action = (const float*)d_in[1];
    const int*   idx    = (const int*)d_in[2];
    const float* W1     = (const float*)d_in[3];
    const float* b1     = (const float*)d_in[4];
    const float* W2s    = (const float*)d_in[5];
    const float* b2s    = (const float*)d_in[6];
    const float* W2a    = (const float*)d_in[7];
    const float* W3     = (const float*)d_in[8];
    const float* b3     = (const float*)d_in[9];
    float* out = (float*)d_out;

    cudaFuncSetAttribute(h1_mma_kernel,  cudaFuncAttributeMaxDynamicSharedMemorySize, H1_SMEM);
    cudaFuncSetAttribute(h2q_mma_kernel, cudaFuncAttributeMaxDynamicSharedMemorySize, H2_SMEM);

    prep_kernel<<<PREP_BLOCKS, 256>>>(state, action, idx, W1, W2s, W2a, b3, out);
    h1_mma_kernel<<<dim3(10, B_TOT / 128), 256, H1_SMEM>>>(idx, b1);
    h2q_mma_kernel<<<dim3(4, B_TOT / 128), 256, H2_SMEM>>>(idx, b2s, W3, out);
}

// round 10
// speedup vs baseline: 1.4065x; 1.4065x over previous
#include <cuda_runtime.h>
#include <cuda_bf16.h>
#include <cstdint>
#include <cstddef>

#define B_TOT 32768
#define D_IN  128
#define A_DIM 16
#define H1D   600
#define H2D   500
#define KP    640
#define G_N   8

// ---- h1 geometry (CK=64, proven R4/R6) ----
#define H1_ROWB   144u
#define H1_AHALF  18432u   // 128*144
#define H1_BHALF  9216u    // 64*144
#define H1_STAGE  (2u*H1_AHALF + 2u*H1_BHALF)   // 55296
#define H1_SMEM   (2*H1_STAGE + 1024)

// ---- h2q geometry: A-only smem (B via fragment LDG) ----
#define H2_ROWB   144u
#define H2_AHALF  18432u
#define H2_ASTAGE (2u*H2_AHALF)      // 36864
#define H2_SMEM   (2*H2_ASTAGE + 1024)

// ---- persistent device scratch ----
__device__ __nv_bfloat16 g_h1hi[(size_t)B_TOT * KP];
__device__ __nv_bfloat16 g_h1lo[(size_t)B_TOT * KP];
__device__ __nv_bfloat16 g_Sh[(size_t)B_TOT * D_IN];
__device__ __nv_bfloat16 g_Sl[(size_t)B_TOT * D_IN];
__device__ __nv_bfloat16 g_W1h[(size_t)G_N * 640 * D_IN];
__device__ __nv_bfloat16 g_W1l[(size_t)G_N * 640 * D_IN];
// B fragments for gemm2: unit = ((kstep*64 + n8)*2 + h)*32 + lane, 8B each (b0|b1<<32)
__device__ uint64_t g_W2f[(size_t)36 * 64 * 2 * 32];      // ksteps 0..35 (k<576)
__device__ uint64_t g_Btf[(size_t)G_N * 4 * 64 * 2 * 32]; // tail k 576..639, per game

// ---------------- helpers ----------------
__device__ __forceinline__ uint32_t smem_u32(const void* p) {
    uint32_t a;
    asm("{ .reg .u64 t; cvta.to.shared.u64 t, %1; cvt.u32.u64 %0, t; }" : "=r"(a) : "l"(p));
    return a;
}
__device__ __forceinline__ void ldm_x4(uint32_t* r, uint32_t addr) {
    asm volatile("ldmatrix.sync.aligned.m8n8.x4.shared.b16 {%0,%1,%2,%3}, [%4];"
                 : "=r"(r[0]), "=r"(r[1]), "=r"(r[2]), "=r"(r[3]) : "r"(addr));
}
__device__ __forceinline__ void mma16816(float* c, const uint32_t* a, const uint32_t* b) {
    asm volatile("mma.sync.aligned.m16n8k16.row.col.f32.bf16.bf16.f32 "
                 "{%0,%1,%2,%3}, {%4,%5,%6,%7}, {%8,%9}, {%0,%1,%2,%3};"
                 : "+f"(c[0]), "+f"(c[1]), "+f"(c[2]), "+f"(c[3])
                 : "r"(a[0]), "r"(a[1]), "r"(a[2]), "r"(a[3]), "r"(b[0]), "r"(b[1]));
}
__device__ __forceinline__ void cp16(uint32_t dst, const void* src) {
    asm volatile("cp.async.cg.shared.global [%0], [%1], 16;" :: "r"(dst), "l"(src) : "memory");
}
__device__ __forceinline__ void cp_commit() { asm volatile("cp.async.commit_group;" ::: "memory"); }
__device__ __forceinline__ void cp_wait0() { asm volatile("cp.async.wait_group 0;" ::: "memory"); }

__device__ __forceinline__ uint32_t pack2(float f0, float f1) {
    uint32_t r;
    asm("cvt.rn.bf16x2.f32 %0, %1, %2;" : "=r"(r) : "f"(f1), "f"(f0));
    return r;
}
__device__ __forceinline__ void split2(float f0, float f1, uint32_t& h, uint32_t& l) {
    h = pack2(f0, f1);
    float h0 = __uint_as_float(h << 16);
    float h1 = __uint_as_float(h & 0xffff0000u);
    l = pack2(f0 - h0, f1 - h1);
}
__device__ __forceinline__ void split8(float4 v0, float4 v1, uint4& H, uint4& L) {
    split2(v0.x, v0.y, H.x, L.x);
    split2(v0.z, v0.w, H.y, L.y);
    split2(v1.x, v1.y, H.z, L.z);
    split2(v1.z, v1.w, H.w, L.w);
}

// ---------------- fused prep kernel ----------------
// [0,128) init_out | [128,256) fill_pad | [256,2304) split_state | [2304,2624) split_W1
// [2624,2912) W2 frags | [2912,3168) Btail frags
#define PREP_BLOCKS 3168
__global__ __launch_bounds__(256) void prep_kernel(const float* __restrict__ state,
                                                   const float* __restrict__ action,
                                                   const int* __restrict__ idx,
                                                   const float* __restrict__ W1,
                                                   const float* __restrict__ W2s,
                                                   const float* __restrict__ W2a,
                                                   const float* __restrict__ b3,
                                                   float* __restrict__ out) {
    const int blk = blockIdx.x;
    const int t = threadIdx.x;
    if (blk < 128) {
        int i = blk * 256 + t;
        out[i] = b3[idx[i]];
    } else if (blk < 256) {
        int b = (blk - 128) * 256 + t;
        const float4* a4 = (const float4*)(action + (size_t)b * A_DIM);
        uint4 H0, L0, H1, L1;
        split8(a4[0], a4[1], H0, L0);
        split8(a4[2], a4[3], H1, L1);
        uint16_t* ph = (uint16_t*)g_h1hi + (size_t)b * KP + 600;
        uint16_t* pl = (uint16_t*)g_h1lo + (size_t)b * KP + 600;
        ((uint4*)ph)[0] = H0; ((uint4*)ph)[1] = H1;
        ((uint4*)pl)[0] = L0; ((uint4*)pl)[1] = L1;
        uint4 z = make_uint4(0, 0, 0, 0);
        ((uint4*)(ph + 16))[0] = z; ((uint4*)(ph + 16))[1] = z; ((uint4*)(ph + 16))[2] = z;
        ((uint4*)(pl + 16))[0] = z; ((uint4*)(pl + 16))[1] = z; ((uint4*)(pl + 16))[2] = z;
    } else if (blk < 2304) {
        size_t e = ((size_t)(blk - 256) * 256 + t) * 8;
        const float4* s4 = (const float4*)(state + e);
        uint4 H, L;
        split8(s4[0], s4[1], H, L);
        *(uint4*)((uint16_t*)g_Sh + e) = H;
        *(uint4*)((uint16_t*)g_Sl + e) = L;
    } else if (blk < 2624) {
        size_t e = ((size_t)(blk - 2304) * 256 + t) * 8;
        int g = (int)(e / (640 * D_IN));
        int r = (int)((e / D_IN) % 640);
        int c = (int)(e % D_IN);
        uint4 H = make_uint4(0, 0, 0, 0), L = H;
        if (r < H1D) {
            const float4* s4 = (const float4*)(W1 + ((size_t)g * H1D + r) * D_IN + c);
            split8(s4[0], s4[1], H, L);
        }
        *(uint4*)((uint16_t*)g_W1h + e) = H;
        *(uint4*)((uint16_t*)g_W1l + e) = L;
    } else if (blk < 2912) {
        // W2 fragment units: u = (kq*64 + n8)*32 + lane, kq in [0,36)
        int u = (blk - 2624) * 256 + t;     // [0, 73728)
        int lane = u & 31;
        int n8 = (u >> 5) & 63;
        int kq = u >> 11;
        int n = n8 * 8 + (lane >> 2);
        int k0 = kq * 16 + (lane & 3) * 2;
        float x0 = 0.f, x1 = 0.f, x2 = 0.f, x3 = 0.f;
        if (n < H2D) {
            const float* w = W2s + (size_t)n * H1D;
            x0 = w[k0]; x1 = w[k0 + 1]; x2 = w[k0 + 8]; x3 = w[k0 + 9];
        }
        uint32_t h0, l0, h1, l1;
        split2(x0, x1, h0, l0);
        split2(x2, x3, h1, l1);
        size_t base = ((size_t)(kq * 64 + n8) * 2) * 32 + lane;
        g_W2f[base]      = (uint64_t)h0 | ((uint64_t)h1 << 32);
        g_W2f[base + 32] = (uint64_t)l0 | ((uint64_t)l1 << 32);
    } else {
        // B tail fragment units: u = (gk*64 + n8)*32 + lane, gk = g*4+kk in [0,32)
        int u = (blk - 2912) * 256 + t;     // [0, 65536)
        int lane = u & 31;
        int n8 = (u >> 5) & 63;
        int gk = u >> 11;
        int g = gk >> 2, kk = gk & 3;
        int n = n8 * 8 + (lane >> 2);
        int c0 = kk * 16 + (lane & 3) * 2;  // local col within 576..639
        float v[4];
        const int off[4] = {0, 1, 8, 9};
        #pragma unroll
        for (int j = 0; j < 4; j++) {
            int tc = 576 + c0 + off[j];
            float x = 0.f;
            if (n < H2D) {
                if (tc < H1D) x = W2s[(size_t)n * H1D + tc];
                else if (tc < H1D + A_DIM) x = W2a[((size_t)g * H2D + n) * A_DIM + (tc - H1D)];
            }
            v[j] = x;
        }
        uint32_t h0, l0, h1, l1;
        split2(v[0], v[1], h0, l0);
        split2(v[2], v[3], h1, l1);
        size_t base = ((size_t)(gk * 64 + n8) * 2) * 32 + lane;
        g_Btf[base]      = (uint64_t)h0 | ((uint64_t)h1 << 32);
        g_Btf[base + 32] = (uint64_t)l0 | ((uint64_t)l1 << 32);
    }
}

// ================= GEMM1 (R6-proven): M=128,N=64,K=128, CK=64, 2 stages =================
#define MMA_STAGE1(sbase, s)                                                       \
    {                                                                              \
        const uint32_t SA = (sbase) + (uint32_t)(s) * H1_STAGE;                    \
        const uint32_t SAh = SA, SAl = SA + H1_AHALF;                              \
        const uint32_t SBh = SA + 2u * H1_AHALF, SBl = SBh + H1_BHALF;             \
        _Pragma("unroll")                                                          \
        for (int kk = 0; kk < 4; kk++) {                                           \
            uint32_t ah[2][4], al[2][4], bh[4][2], bl[4][2];                       \
            _Pragma("unroll")                                                      \
            for (int mf = 0; mf < 2; mf++) {                                       \
                ldm_x4(ah[mf], SAh + aoff + mf * 2304u + kk * 32u);                \
                ldm_x4(al[mf], SAl + aoff + mf * 2304u + kk * 32u);                \
            }                                                                      \
            _Pragma("unroll")                                                      \
            for (int nq = 0; nq < 2; nq++) {                                       \
                uint32_t t[4];                                                     \
                ldm_x4(t, SBh + boff + nq * 2304u + kk * 32u);                     \
                bh[nq * 2][0] = t[0]; bh[nq * 2][1] = t[2];                        \
                bh[nq * 2 + 1][0] = t[1]; bh[nq * 2 + 1][1] = t[3];                \
                ldm_x4(t, SBl + boff + nq * 2304u + kk * 32u);                     \
                bl[nq * 2][0] = t[0]; bl[nq * 2][1] = t[2];                        \
                bl[nq * 2 + 1][0] = t[1]; bl[nq * 2 + 1][1] = t[3];                \
            }                                                                      \
            _Pragma("unroll")                                                      \
            for (int mf = 0; mf < 2; mf++)                                         \
                _Pragma("unroll")                                                  \
                for (int nf = 0; nf < 4; nf++) {                                   \
                    mma16816(C[mf][nf], ah[mf], bh[nf]);                           \
                    mma16816(C[mf][nf], ah[mf], bl[nf]);                           \
                    mma16816(C[mf][nf], al[mf], bh[nf]);                           \
                }                                                                  \
        }                                                                          \
    }

__global__ __launch_bounds__(256, 2) void h1_mma_kernel(const int* __restrict__ idx,
                                                        const float* __restrict__ b1) {
    extern __shared__ char dsm[];
    const uint32_t sbase = smem_u32(dsm);
    float* sb1 = (float*)(dsm + 2 * H1_STAGE);
    int* sidx = (int*)(sb1 + 64);
    const int tid = threadIdx.x, lane = tid & 31, wid = tid >> 5;
    const int n0 = blockIdx.x * 64, b0 = blockIdx.y * 128;
    if (tid < 128) sidx[tid] = idx[b0 + tid];
    __syncthreads();
    const int g_lo = sidx[0], g_hi = sidx[127];
    const int m_base = (wid >> 1) * 32, n_base = (wid & 1) * 32;
    const uint32_t aoff = (uint32_t)(m_base + (lane & 15)) * H1_ROWB + (uint32_t)((lane >> 4) * 16);
    const uint32_t boff = (uint32_t)(n_base + (lane & 15)) * H1_ROWB + (uint32_t)((lane >> 4) * 16);

    for (int g = g_lo; g <= g_hi; ++g) {
        if (tid < 64) { int n = n0 + tid; sb1[tid] = (n < H1D) ? b1[(size_t)g * H1D + n] : 0.f; }
        auto issue = [&](int kc, int s) {
            #pragma unroll
            for (int i = 0; i < 8; i++) {
                int bid = tid + i * 256;
                int arr = bid >> 10, rem = bid & 1023;
                int row = rem >> 3, q = rem & 7;
                const __nv_bfloat16* src = (arr ? g_Sl : g_Sh) + (size_t)(b0 + row) * D_IN + kc * 64 + q * 8;
                cp16(sbase + (uint32_t)s * H1_STAGE + (uint32_t)arr * H1_AHALF + row * H1_ROWB + q * 16u, src);
            }
            #pragma unroll
            for (int i = 0; i < 4; i++) {
                int bid = tid + i * 256;
                int arr = bid >> 9, rem = bid & 511;
                int row = rem >> 3, q = rem & 7;
                const __nv_bfloat16* src = (arr ? g_W1l : g_W1h) + ((size_t)g * 640 + n0 + row) * D_IN + kc * 64 + q * 8;
                cp16(sbase + (uint32_t)s * H1_STAGE + 2u * H1_AHALF + (uint32_t)arr * H1_BHALF + row * H1_ROWB + q * 16u, src);
            }
            cp_commit();
        };
        float C[2][4][4];
        #pragma unroll
        for (int mf = 0; mf < 2; mf++)
            #pragma unroll
            for (int nf = 0; nf < 4; nf++)
                #pragma unroll
                for (int e = 0; e < 4; e++) C[mf][nf][e] = 0.f;

        issue(0, 0);
        cp_wait0();
        __syncthreads();
        issue(1, 1);
        MMA_STAGE1(sbase, 0);
        cp_wait0();
        __syncthreads();
        MMA_STAGE1(sbase, 1);

        #pragma unroll
        for (int mf = 0; mf < 2; mf++)
            #pragma unroll
            for (int half = 0; half < 2; half++) {
                int r = m_base + mf * 16 + (lane >> 2) + half * 8;
                if (sidx[r] == g) {
                    size_t base = (size_t)(b0 + r) * KP;
                    #pragma unroll
                    for (int nf = 0; nf < 4; nf++) {
                        int lc = n_base + nf * 8 + 2 * (lane & 3);
                        int n = n0 + lc;
                        if (n < H1D) {
                            float v0 = fmaxf(C[mf][nf][half * 2 + 0] + sb1[lc], 0.f);
                            float v1 = fmaxf(C[mf][nf][half * 2 + 1] + sb1[lc + 1], 0.f);
                            uint32_t h, l;
                            split2(v0, v1, h, l);
                            *(uint32_t*)(g_h1hi + base + n) = h;
                            *(uint32_t*)(g_h1lo + base + n) = l;
                        }
                    }
                }
            }
        __syncthreads();
    }
}

// ========== GEMM2: M=128 x N=64, CK=64; A via cp.async+LDSM, B via fragment LDG ==========
__global__ __launch_bounds__(256, 2) void h2q_mma_kernel(const int* __restrict__ idx,
                                                         const float* __restrict__ b2s,
                                                         const float* __restrict__ W3,
                                                         float* __restrict__ out) {
    extern __shared__ char dsm[];
    const uint32_t sbase = smem_u32(dsm);
    float* sb2 = (float*)(dsm + 2 * H2_ASTAGE);
    float* sw3 = sb2 + 64;
    int* sidx = (int*)(sw3 + 64);
    const int tid = threadIdx.x, lane = tid & 31, wid = tid >> 5;
    const int n0 = blockIdx.x * 64, b0 = blockIdx.y * 128;
    if (tid < 128) sidx[tid] = idx[b0 + tid];
    if (tid < 64) { int n = n0 + tid; sb2[tid] = (n < H2D) ? b2s[n] : 0.f; }
    __syncthreads();
    const int g_lo = sidx[0], g_hi = sidx[127];
    const int m_base = (wid >> 1) * 32, n_base = (wid & 1) * 32;
    const uint32_t aoff = (uint32_t)(m_base + (lane & 15)) * H2_ROWB + (uint32_t)((lane >> 4) * 16);
    const int ngbase = (n0 >> 3) + (n_base >> 3);

    for (int g = g_lo; g <= g_hi; ++g) {
        if (tid < 64) { int n = n0 + tid; sw3[tid] = (n < H2D) ? W3[(size_t)g * H2D + n] : 0.f; }

        auto issueA = [&](int kc, int s) {
            #pragma unroll
            for (int i = 0; i < 8; i++) {
                int bid = tid + i * 256;
                int arr = bid >> 10, rem = bid & 1023;
                int row = rem >> 3, q = rem & 7;
                const __nv_bfloat16* src = (arr ? g_h1lo : g_h1hi) + (size_t)(b0 + row) * KP + kc * 64 + q * 8;
                cp16(sbase + (uint32_t)s * H2_ASTAGE + (uint32_t)arr * H2_AHALF + row * H2_ROWB + q * 16u, src);
            }
            cp_commit();
        };
        // load B fragments for (kc, kk) into bb
        auto loadB = [&](uint32_t (&bb)[4][2][2], int kc, int kk) {
            const uint64_t* src;
            size_t base;
            if (kc < 9) {
                base = ((size_t)((kc * 4 + kk) * 64 + ngbase) * 2) * 32 + lane;
                src = g_W2f;
            } else {
                base = ((size_t)((g * 4 + kk) * 64 + ngbase) * 2) * 32 + lane;
                src = g_Btf;
            }
            #pragma unroll
            for (int nf = 0; nf < 4; nf++)
                #pragma unroll
                for (int h = 0; h < 2; h++) {
                    uint64_t v = __ldg(src + base + (size_t)(nf * 2 + h) * 32);
                    bb[nf][h][0] = (uint32_t)v;
                    bb[nf][h][1] = (uint32_t)(v >> 32);
                }
        };

        float C[2][4][4];
        #pragma unroll
        for (int mf = 0; mf < 2; mf++)
            #pragma unroll
            for (int nf = 0; nf < 4; nf++)
                #pragma unroll
                for (int e = 0; e < 4; e++) C[mf][nf][e] = 0.f;

        uint32_t bb[2][4][2][2];
        loadB(bb[0], 0, 0);
        issueA(0, 0);
        for (int kc = 0; kc < 10; ++kc) {
            cp_wait0();
            __syncthreads();              // chunk kc A visible; all warps done with other stage
            if (kc < 9) issueA(kc + 1, (kc + 1) & 1);
            const uint32_t SA = sbase + (uint32_t)(kc & 1) * H2_ASTAGE;
            const uint32_t SAh = SA, SAl = SA + H2_AHALF;
            #pragma unroll
            for (int kk = 0; kk < 4; kk++) {
                const int p = kk & 1;
                if (kk < 3)      loadB(bb[p ^ 1], kc, kk + 1);
                else if (kc < 9) loadB(bb[p ^ 1], kc + 1, 0);
                uint32_t ah[2][4], al[2][4];
                #pragma unroll
                for (int mf = 0; mf < 2; mf++) {
                    ldm_x4(ah[mf], SAh + aoff + mf * 2304u + kk * 32u);
                    ldm_x4(al[mf], SAl + aoff + mf * 2304u + kk * 32u);
                }
                #pragma unroll
                for (int mf = 0; mf < 2; mf++)
                    #pragma unroll
                    for (int nf = 0; nf < 4; nf++) {
                        mma16816(C[mf][nf], ah[mf], bb[p][nf][0]);
                        mma16816(C[mf][nf], ah[mf], bb[p][nf][1]);
                        mma16816(C[mf][nf], al[mf], bb[p][nf][0]);
                    }
            }
        }

        // epilogue: relu(+b2s) . W3, quad-reduce, atomicAdd
        #pragma unroll
        for (int mf = 0; mf < 2; mf++)
            #pragma unroll
            for (int half = 0; half < 2; half++) {
                int r = m_base + mf * 16 + (lane >> 2) + half * 8;
                float qp = 0.f;
                #pragma unroll
                for (int nf = 0; nf < 4; nf++) {
                    int lc = n_base + nf * 8 + 2 * (lane & 3);
                    qp += fmaxf(C[mf][nf][half * 2 + 0] + sb2[lc], 0.f) * sw3[lc];
                    qp += fmaxf(C[mf][nf][half * 2 + 1] + sb2[lc + 1], 0.f) * sw3[lc + 1];
                }
                qp += __shfl_xor_sync(0xffffffffu, qp, 1);
                qp += __shfl_xor_sync(0xffffffffu, qp, 2);
                if ((lane & 3) == 0 && sidx[r] == g) atomicAdd(out + b0 + r, qp);
            }
        __syncthreads();
    }
}

extern "C" void kernel_launch(void* const* d_in, const int* in_sizes, int n_in,
                              void* d_out, int out_size) {
    const float* state  = (const float*)d_in[0];
    const float* action = (const float*)d_in[1];
    const int*   idx    = (const int*)d_in[2];
    const float* W1     = (const float*)d_in[3];
    const float* b1     = (const float*)d_in[4];
    const float* W2s    = (const float*)d_in[5];
    const float* b2s    = (const float*)d_in[6];
    const float* W2a    = (const float*)d_in[7];
    const float* W3     = (const float*)d_in[8];
    const float* b3     = (const float*)d_in[9];
    float* out = (float*)d_out;

    cudaFuncSetAttribute(h1_mma_kernel,  cudaFuncAttributeMaxDynamicSharedMemorySize, H1_SMEM);
    cudaFuncSetAttribute(h2q_mma_kernel, cudaFuncAttributeMaxDynamicSharedMemorySize, H2_SMEM);

    prep_kernel<<<PREP_BLOCKS, 256>>>(state, action, idx, W1, W2s, W2a, b3, out);
    h1_mma_kernel<<<dim3(10, B_TOT / 128), 256, H1_SMEM>>>(idx, b1);
    h2q_mma_kernel<<<dim3(8, B_TOT / 128), 256, H2_SMEM>>>(idx, b2s, W3, out);
}